// round 2
// baseline (speedup 1.0000x reference)
#include <cuda_runtime.h>
#include <cuda_bf16.h>

// Problem constants: x [4, 2048, 1024] fp32; W_q/W_k/W_v [1024, 1024] fp32.
// out [4, 2048, 1024] fp32.
#define BATCH 4
#define SEQ   2048
#define DIM   1024

// Scratch (static device globals -- allocation-free per harness rules).
__device__ float g_Q[(long long)BATCH * SEQ * DIM];  // 32 MB
__device__ float g_K[(long long)BATCH * SEQ * DIM];  // 32 MB
__device__ float g_V[(long long)BATCH * SEQ * DIM];  // 32 MB
__device__ float g_S[(long long)BATCH * SEQ * SEQ];  // 64 MB

// ---------------------------------------------------------------------------
// Tiled SGEMM: C = alpha * A * op(B)
//   A: [M, K] row-major
//   BT = true : B is [N, K] row-major, C = alpha * A * B^T   (QKV, Q*K^T)
//   BT = false: B is [K, N] row-major, C = alpha * A * B     (P*V)
// Block tile 128x128, K-tile 16, 256 threads, 8x8 per-thread microkernel.
// All dims assumed multiples of tile sizes (true for this problem).
// ---------------------------------------------------------------------------
constexpr int BM = 128, BN = 128, BK = 16, TM = 8, TN = 8;

template <bool BT>
__global__ __launch_bounds__(256) void sgemm_kernel(
    const float* __restrict__ A, const float* __restrict__ B, float* __restrict__ C,
    int M, int N, int K, float alpha,
    long long sA, long long sB, long long sC)
{
    A += (long long)blockIdx.z * sA;
    B += (long long)blockIdx.z * sB;
    C += (long long)blockIdx.z * sC;

    __shared__ float As[BK][BM + 4];  // +4 pad: kills transpose-store conflicts
    __shared__ float Bs[BK][BN + 4];

    const int tid = threadIdx.x;
    const int tx = tid & 15;          // 16 thread-cols
    const int ty = tid >> 4;          // 16 thread-rows

    const int rowBase = blockIdx.y * BM;
    const int colBase = blockIdx.x * BN;

    float acc[TM][TN];
#pragma unroll
    for (int i = 0; i < TM; i++)
#pragma unroll
        for (int j = 0; j < TN; j++) acc[i][j] = 0.f;

    for (int k0 = 0; k0 < K; k0 += BK) {
        // --- load A tile (BM x BK): 512 float4, 2 per thread, store transposed
#pragma unroll
        for (int l = 0; l < 2; l++) {
            int f = tid + l * 256;
            int r = f >> 2;           // 4 float4 per row (BK=16)
            int c4 = f & 3;
            float4 v = *(const float4*)&A[(long long)(rowBase + r) * K + k0 + c4 * 4];
            As[c4 * 4 + 0][r] = v.x;
            As[c4 * 4 + 1][r] = v.y;
            As[c4 * 4 + 2][r] = v.z;
            As[c4 * 4 + 3][r] = v.w;
        }
        // --- load B tile
        if (BT) {
            // B [N, K] row-major: same transposed-store pattern as A
#pragma unroll
            for (int l = 0; l < 2; l++) {
                int f = tid + l * 256;
                int r = f >> 2;
                int c4 = f & 3;
                float4 v = *(const float4*)&B[(long long)(colBase + r) * K + k0 + c4 * 4];
                Bs[c4 * 4 + 0][r] = v.x;
                Bs[c4 * 4 + 1][r] = v.y;
                Bs[c4 * 4 + 2][r] = v.z;
                Bs[c4 * 4 + 3][r] = v.w;
            }
        } else {
            // B [K, N] row-major: natural layout, float4 direct store
#pragma unroll
            for (int l = 0; l < 2; l++) {
                int f = tid + l * 256;
                int kr = f >> 5;      // 32 float4 per row (BN=128)
                int n4 = f & 31;
                float4 v = *(const float4*)&B[(long long)(k0 + kr) * N + colBase + n4 * 4];
                *(float4*)&Bs[kr][n4 * 4] = v;
            }
        }
        __syncthreads();

#pragma unroll
        for (int kk = 0; kk < BK; kk++) {
            float a[TM], b[TN];
#pragma unroll
            for (int i = 0; i < TM; i++) a[i] = As[kk][ty * TM + i];
#pragma unroll
            for (int j = 0; j < TN; j++) b[j] = Bs[kk][tx * TN + j];
#pragma unroll
            for (int i = 0; i < TM; i++)
#pragma unroll
                for (int j = 0; j < TN; j++)
                    acc[i][j] += a[i] * b[j];
        }
        __syncthreads();
    }

#pragma unroll
    for (int i = 0; i < TM; i++) {
        long long r = rowBase + ty * TM + i;
#pragma unroll
        for (int j = 0; j < TN; j += 4) {
            float4 v;
            v.x = acc[i][j + 0] * alpha;
            v.y = acc[i][j + 1] * alpha;
            v.z = acc[i][j + 2] * alpha;
            v.w = acc[i][j + 3] * alpha;
            *(float4*)&C[r * N + colBase + tx * TN + j] = v;
        }
    }
}

// ---------------------------------------------------------------------------
// Row softmax over SEQ=2048 elements. One block (256 threads) per row.
// ---------------------------------------------------------------------------
__global__ __launch_bounds__(256) void softmax_kernel(float* __restrict__ S)
{
    float* p = S + (long long)blockIdx.x * SEQ;
    const int tid = threadIdx.x;

    float v[8];
    float lmax = -__FLT_MAX__;
#pragma unroll
    for (int l = 0; l < 8; l++) {
        v[l] = p[tid + l * 256];
        lmax = fmaxf(lmax, v[l]);
    }

    __shared__ float red[8];
#pragma unroll
    for (int o = 16; o; o >>= 1) lmax = fmaxf(lmax, __shfl_xor_sync(~0u, lmax, o));
    if ((tid & 31) == 0) red[tid >> 5] = lmax;
    __syncthreads();
    if (tid == 0) {
        float m = red[0];
#pragma unroll
        for (int i = 1; i < 8; i++) m = fmaxf(m, red[i]);
        red[0] = m;
    }
    __syncthreads();
    const float m = red[0];
    __syncthreads();

    float lsum = 0.f;
#pragma unroll
    for (int l = 0; l < 8; l++) {
        v[l] = __expf(v[l] - m);
        lsum += v[l];
    }
#pragma unroll
    for (int o = 16; o; o >>= 1) lsum += __shfl_xor_sync(~0u, lsum, o);
    if ((tid & 31) == 0) red[tid >> 5] = lsum;
    __syncthreads();
    if (tid == 0) {
        float s = red[0];
#pragma unroll
        for (int i = 1; i < 8; i++) s += red[i];
        red[0] = s;
    }
    __syncthreads();
    const float inv = 1.f / red[0];

#pragma unroll
    for (int l = 0; l < 8; l++) p[tid + l * 256] = v[l] * inv;
}

// ---------------------------------------------------------------------------
extern "C" void kernel_launch(void* const* d_in, const int* in_sizes, int n_in,
                              void* d_out, int out_size)
{
    const float* x  = (const float*)d_in[0];
    const float* Wq = (const float*)d_in[1];
    const float* Wk = (const float*)d_in[2];
    const float* Wv = (const float*)d_in[3];
    float* out = (float*)d_out;

    float *Q, *K, *V, *S;
    cudaGetSymbolAddress((void**)&Q, g_Q);
    cudaGetSymbolAddress((void**)&K, g_K);
    cudaGetSymbolAddress((void**)&V, g_V);
    cudaGetSymbolAddress((void**)&S, g_S);

    const dim3 blk(256);
    const int  M_qkv = BATCH * SEQ;  // 8192

    // 1) Q/K/V = x @ W^T   (flattened [8192, 1024] x [1024, 1024]^T)
    dim3 g_qkv(DIM / BN, M_qkv / BM, 1);
    sgemm_kernel<true><<<g_qkv, blk>>>(x, Wq, Q, M_qkv, DIM, DIM, 1.f, 0, 0, 0);
    sgemm_kernel<true><<<g_qkv, blk>>>(x, Wk, K, M_qkv, DIM, DIM, 1.f, 0, 0, 0);
    sgemm_kernel<true><<<g_qkv, blk>>>(x, Wv, V, M_qkv, DIM, DIM, 1.f, 0, 0, 0);

    // 2) S = (Q @ K^T) / sqrt(1024), batched over 4
    dim3 g_s(SEQ / BN, SEQ / BM, BATCH);
    sgemm_kernel<true><<<g_s, blk>>>(Q, K, S, SEQ, SEQ, DIM, 0.03125f,
                                     (long long)SEQ * DIM, (long long)SEQ * DIM,
                                     (long long)SEQ * SEQ);

    // 3) row softmax
    softmax_kernel<<<BATCH * SEQ, 256>>>(S);

    // 4) out = P @ V, batched over 4
    dim3 g_o(DIM / BN, SEQ / BM, BATCH);
    sgemm_kernel<false><<<g_o, blk>>>(S, V, out, SEQ, DIM, SEQ, 1.f,
                                      (long long)SEQ * SEQ, (long long)SEQ * DIM,
                                      (long long)SEQ * DIM);
}

// round 6
// speedup vs baseline: 2.9766x; 2.9766x over previous
#include <cuda_runtime.h>
#include <cuda_bf16.h>
#include <cstdint>

#define BATCH 4
#define SEQ   2048
#define DIM   1024
#define MTOT  (BATCH * SEQ)

// ---------------------------------------------------------------------------
// Static device scratch (allocation-free per harness rules)
// ---------------------------------------------------------------------------
__device__ __nv_bfloat16 g_xhi[(size_t)MTOT * DIM], g_xlo[(size_t)MTOT * DIM];
__device__ __nv_bfloat16 g_Wqhi[DIM * DIM], g_Wqlo[DIM * DIM];
__device__ __nv_bfloat16 g_Wkhi[DIM * DIM], g_Wklo[DIM * DIM];
__device__ __nv_bfloat16 g_Wvhi[DIM * DIM], g_Wvlo[DIM * DIM];
__device__ __nv_bfloat16 g_Qhi[(size_t)MTOT * DIM], g_Qlo[(size_t)MTOT * DIM];
__device__ __nv_bfloat16 g_Khi[(size_t)MTOT * DIM], g_Klo[(size_t)MTOT * DIM];
__device__ __nv_bfloat16 g_Vthi[(size_t)DIM * MTOT], g_Vtlo[(size_t)DIM * MTOT];  // [DIM, MTOT]
__device__ float         g_S[(size_t)BATCH * SEQ * SEQ];
__device__ __nv_bfloat16 g_Phi[(size_t)BATCH * SEQ * SEQ], g_Plo[(size_t)BATCH * SEQ * SEQ];

// ---------------------------------------------------------------------------
// PTX helpers (portable sm_80+ subset only -- NO tcgen05, which ptxas rejects
// on the harness's compute_103 target)
// ---------------------------------------------------------------------------
__device__ __forceinline__ uint32_t smem_u32(const void* p) {
    uint32_t a;
    asm("{ .reg .u64 t; cvta.to.shared.u64 t, %1; cvt.u32.u64 %0, t; }" : "=r"(a) : "l"(p));
    return a;
}

#define CP16(dst, src) \
    asm volatile("cp.async.cg.shared.global [%0], [%1], 16;" :: "r"(dst), "l"(src))
#define CP_COMMIT()  asm volatile("cp.async.commit_group;" ::: "memory")
#define CP_WAIT(n)   asm volatile("cp.async.wait_group %0;" :: "n"(n) : "memory")

#define LDSM_X4(r0, r1, r2, r3, addr)                                        \
    asm volatile("ldmatrix.sync.aligned.m8n8.x4.shared.b16 {%0,%1,%2,%3}, [%4];" \
                 : "=r"(r0), "=r"(r1), "=r"(r2), "=r"(r3) : "r"(addr))

#define MMA16816(d, a, b)                                                    \
    asm volatile("mma.sync.aligned.m16n8k16.row.col.f32.bf16.bf16.f32 "       \
                 "{%0,%1,%2,%3}, {%4,%5,%6,%7}, {%8,%9}, {%0,%1,%2,%3};"      \
                 : "+f"((d)[0]), "+f"((d)[1]), "+f"((d)[2]), "+f"((d)[3])     \
                 : "r"((a)[0]), "r"((a)[1]), "r"((a)[2]), "r"((a)[3]),        \
                   "r"((b)[0]), "r"((b)[1]))

// ---------------------------------------------------------------------------
// Split-precision HMMA GEMM: C = scale * (A * B^T), A [M,K], B [N,K] (K-major),
// both as (hi, lo) bf16 pairs; D = Ahi*Bhi + Ahi*Blo + Alo*Bhi (fp32 accum).
// Block tile 128x128, K-tile 64, 8 warps (warp tile 64x32), double-buffered
// cp.async, SW128-swizzled smem, ldmatrix fragment loads.
// ---------------------------------------------------------------------------
enum { EPI_F32 = 0, EPI_SPLIT = 1, EPI_SPLIT_T = 2 };

constexpr int TILE_B  = 16384;           // one 128x64 bf16 tile (SW128 rows)
constexpr int STAGE_B = 4 * TILE_B;      // Ahi, Alo, Bhi, Blo
constexpr int SMEM_BYTES = 2 * STAGE_B;  // 131072

template <int EPI>
__global__ __launch_bounds__(256, 1) void wgemm(
    const __nv_bfloat16* __restrict__ Ahi, const __nv_bfloat16* __restrict__ Alo,
    const __nv_bfloat16* __restrict__ Bhi, const __nv_bfloat16* __restrict__ Blo,
    float* __restrict__ outF, __nv_bfloat16* __restrict__ outHi, __nv_bfloat16* __restrict__ outLo,
    int K, int ldA, int ldB, int ldC, float scale,
    long long sA, long long sB, long long sC)
{
    extern __shared__ __align__(1024) char smem[];
    const uint32_t sb = smem_u32(smem);

    const int tid = threadIdx.x, wid = tid >> 5, lane = tid & 31;
    const int bz = blockIdx.z;
    Ahi += (long long)bz * sA;  Alo += (long long)bz * sA;
    Bhi += (long long)bz * sB;  Blo += (long long)bz * sB;
    if (EPI == EPI_F32) outF += (long long)bz * sC;
    else { outHi += (long long)bz * sC; outLo += (long long)bz * sC; }

    const int rowBase = blockIdx.y * 128;
    const int colBase = blockIdx.x * 128;
    const int warp_m = (wid >> 2) * 64;   // 2 warp-rows
    const int warp_n = (wid & 3) * 32;    // 4 warp-cols

    float acc[4][4][4];
#pragma unroll
    for (int mi = 0; mi < 4; mi++)
#pragma unroll
        for (int ni = 0; ni < 4; ni++)
#pragma unroll
            for (int q = 0; q < 4; q++) acc[mi][ni][q] = 0.f;

    const int nK = K >> 6;

    auto load_stage = [&](int i) {
        const uint32_t toff = sb + (i & 1) * STAGE_B;
        const int k0 = i << 6;
#pragma unroll
        for (int l = 0; l < 4; l++) {
            const int idx = tid + l * 256;
            const int r = idx >> 3, sg = idx & 7;
            const uint32_t d = toff + r * 128 + ((sg ^ (r & 7)) << 4);
            const size_t ka = (size_t)(rowBase + r) * ldA + k0 + sg * 8;
            const size_t kb = (size_t)(colBase + r) * ldB + k0 + sg * 8;
            CP16(d,              Ahi + ka);
            CP16(d + TILE_B,     Alo + ka);
            CP16(d + 2 * TILE_B, Bhi + kb);
            CP16(d + 3 * TILE_B, Blo + kb);
        }
        CP_COMMIT();
    };

    load_stage(0);

    for (int i = 0; i < nK; i++) {
        if (i + 1 < nK) { load_stage(i + 1); CP_WAIT(1); }
        else            { CP_WAIT(0); }
        __syncthreads();

        const uint32_t so = sb + (i & 1) * STAGE_B;

#pragma unroll
        for (int s = 0; s < 4; s++) {          // four k16 steps within k64
            uint32_t ah[4][4], al[4][4];
#pragma unroll
            for (int mi = 0; mi < 4; mi++) {
                const int r = warp_m + mi * 16 + (lane & 15);
                const int c = s * 2 + (lane >> 4);
                const uint32_t a = so + r * 128 + ((c ^ (r & 7)) << 4);
                LDSM_X4(ah[mi][0], ah[mi][1], ah[mi][2], ah[mi][3], a);
                LDSM_X4(al[mi][0], al[mi][1], al[mi][2], al[mi][3], a + TILE_B);
            }
            uint32_t bh[4][2], bl[4][2];
#pragma unroll
            for (int nj = 0; nj < 2; nj++) {
                const int r = warp_n + nj * 16 + (lane & 7) + ((lane >> 4) << 3);
                const int c = s * 2 + ((lane >> 3) & 1);
                const uint32_t a = so + 2 * TILE_B + r * 128 + ((c ^ (r & 7)) << 4);
                uint32_t t0, t1, t2, t3;
                LDSM_X4(t0, t1, t2, t3, a);
                bh[nj * 2][0] = t0; bh[nj * 2][1] = t1;
                bh[nj * 2 + 1][0] = t2; bh[nj * 2 + 1][1] = t3;
                LDSM_X4(t0, t1, t2, t3, a + TILE_B);
                bl[nj * 2][0] = t0; bl[nj * 2][1] = t1;
                bl[nj * 2 + 1][0] = t2; bl[nj * 2 + 1][1] = t3;
            }
#pragma unroll
            for (int mi = 0; mi < 4; mi++)
#pragma unroll
                for (int ni = 0; ni < 4; ni++) {
                    MMA16816(acc[mi][ni], ah[mi], bh[ni]);
                    MMA16816(acc[mi][ni], ah[mi], bl[ni]);
                    MMA16816(acc[mi][ni], al[mi], bh[ni]);
                }
        }
        __syncthreads();
    }

    // ---------------- epilogue ----------------
#pragma unroll
    for (int mi = 0; mi < 4; mi++) {
#pragma unroll
        for (int ni = 0; ni < 4; ni++) {
            const float* a = acc[mi][ni];
            const int row = rowBase + warp_m + mi * 16 + (lane >> 2);
            const int col = colBase + warp_n + ni * 8 + (lane & 3) * 2;
            if (EPI == EPI_F32) {
                float2 v0 = make_float2(a[0] * scale, a[1] * scale);
                float2 v1 = make_float2(a[2] * scale, a[3] * scale);
                *(float2*)&outF[(size_t)row * ldC + col] = v0;
                *(float2*)&outF[(size_t)(row + 8) * ldC + col] = v1;
            } else if (EPI == EPI_SPLIT) {
#pragma unroll
                for (int h = 0; h < 2; h++) {      // two 8-row halves
                    const float d0 = a[h * 2 + 0], d1 = a[h * 2 + 1];
                    const __nv_bfloat16 h0 = __float2bfloat16(d0);
                    const __nv_bfloat16 h1 = __float2bfloat16(d1);
                    __nv_bfloat162 hp, lp;
                    hp.x = h0; hp.y = h1;
                    lp.x = __float2bfloat16(d0 - __bfloat162float(h0));
                    lp.y = __float2bfloat16(d1 - __bfloat162float(h1));
                    const size_t o = (size_t)(row + h * 8) * ldC + col;
                    *(__nv_bfloat162*)&outHi[o] = hp;
                    *(__nv_bfloat162*)&outLo[o] = lp;
                }
            } else {  // EPI_SPLIT_T: out[col][row]
#pragma unroll
                for (int q = 0; q < 4; q++) {
                    const int r2 = row + ((q >> 1) << 3);
                    const int c2 = col + (q & 1);
                    const float d = a[q];
                    const __nv_bfloat16 h = __float2bfloat16(d);
                    outHi[(size_t)c2 * ldC + r2] = h;
                    outLo[(size_t)c2 * ldC + r2] =
                        __float2bfloat16(d - __bfloat162float(h));
                }
            }
        }
    }
}

// ---------------------------------------------------------------------------
// fp32 -> (hi, lo) bf16 split, vectorized
// ---------------------------------------------------------------------------
__global__ __launch_bounds__(256) void split_kernel(
    const float* __restrict__ in, __nv_bfloat16* __restrict__ hi,
    __nv_bfloat16* __restrict__ lo, int n4)
{
    const int i4 = blockIdx.x * 256 + threadIdx.x;
    if (i4 >= n4) return;
    const int i = i4 * 4;
    const float4 v = *(const float4*)&in[i];
    __align__(8) __nv_bfloat16 h[4];
    __align__(8) __nv_bfloat16 l[4];
    const float f[4] = {v.x, v.y, v.z, v.w};
#pragma unroll
    for (int q = 0; q < 4; q++) {
        h[q] = __float2bfloat16(f[q]);
        l[q] = __float2bfloat16(f[q] - __bfloat162float(h[q]));
    }
    *(uint2*)&hi[i] = *(uint2*)h;
    *(uint2*)&lo[i] = *(uint2*)l;
}

// ---------------------------------------------------------------------------
// Row softmax over SEQ=2048, emits split bf16 P
// ---------------------------------------------------------------------------
__global__ __launch_bounds__(256) void softmax_split_kernel(
    const float* __restrict__ S, __nv_bfloat16* __restrict__ Phi,
    __nv_bfloat16* __restrict__ Plo)
{
    const size_t off = (size_t)blockIdx.x * SEQ;
    const float* p = S + off;
    const int tid = threadIdx.x;

    float v[8];
    float lmax = -__FLT_MAX__;
#pragma unroll
    for (int l = 0; l < 8; l++) { v[l] = p[tid + l * 256]; lmax = fmaxf(lmax, v[l]); }

    __shared__ float red[8];
#pragma unroll
    for (int o = 16; o; o >>= 1) lmax = fmaxf(lmax, __shfl_xor_sync(~0u, lmax, o));
    if ((tid & 31) == 0) red[tid >> 5] = lmax;
    __syncthreads();
    if (tid == 0) {
        float m = red[0];
#pragma unroll
        for (int i = 1; i < 8; i++) m = fmaxf(m, red[i]);
        red[0] = m;
    }
    __syncthreads();
    const float m = red[0];
    __syncthreads();

    float lsum = 0.f;
#pragma unroll
    for (int l = 0; l < 8; l++) { v[l] = __expf(v[l] - m); lsum += v[l]; }
#pragma unroll
    for (int o = 16; o; o >>= 1) lsum += __shfl_xor_sync(~0u, lsum, o);
    if ((tid & 31) == 0) red[tid >> 5] = lsum;
    __syncthreads();
    if (tid == 0) {
        float s = red[0];
#pragma unroll
        for (int i = 1; i < 8; i++) s += red[i];
        red[0] = s;
    }
    __syncthreads();
    const float inv = 1.f / red[0];

#pragma unroll
    for (int l = 0; l < 8; l++) {
        const float w = v[l] * inv;
        const __nv_bfloat16 h = __float2bfloat16(w);
        Phi[off + tid + l * 256] = h;
        Plo[off + tid + l * 256] = __float2bfloat16(w - __bfloat162float(h));
    }
}

// ---------------------------------------------------------------------------
extern "C" void kernel_launch(void* const* d_in, const int* in_sizes, int n_in,
                              void* d_out, int out_size)
{
    const float* x  = (const float*)d_in[0];
    const float* Wq = (const float*)d_in[1];
    const float* Wk = (const float*)d_in[2];
    const float* Wv = (const float*)d_in[3];
    float* out = (float*)d_out;

    __nv_bfloat16 *xhi, *xlo, *Wqhi, *Wqlo, *Wkhi, *Wklo, *Wvhi, *Wvlo;
    __nv_bfloat16 *Qhi, *Qlo, *Khi, *Klo, *Vthi, *Vtlo, *Phi, *Plo;
    float* S;
    cudaGetSymbolAddress((void**)&xhi, g_xhi);   cudaGetSymbolAddress((void**)&xlo, g_xlo);
    cudaGetSymbolAddress((void**)&Wqhi, g_Wqhi); cudaGetSymbolAddress((void**)&Wqlo, g_Wqlo);
    cudaGetSymbolAddress((void**)&Wkhi, g_Wkhi); cudaGetSymbolAddress((void**)&Wklo, g_Wklo);
    cudaGetSymbolAddress((void**)&Wvhi, g_Wvhi); cudaGetSymbolAddress((void**)&Wvlo, g_Wvlo);
    cudaGetSymbolAddress((void**)&Qhi, g_Qhi);   cudaGetSymbolAddress((void**)&Qlo, g_Qlo);
    cudaGetSymbolAddress((void**)&Khi, g_Khi);   cudaGetSymbolAddress((void**)&Klo, g_Klo);
    cudaGetSymbolAddress((void**)&Vthi, g_Vthi); cudaGetSymbolAddress((void**)&Vtlo, g_Vtlo);
    cudaGetSymbolAddress((void**)&Phi, g_Phi);   cudaGetSymbolAddress((void**)&Plo, g_Plo);
    cudaGetSymbolAddress((void**)&S, g_S);

    cudaFuncSetAttribute(wgemm<EPI_F32>,     cudaFuncAttributeMaxDynamicSharedMemorySize, SMEM_BYTES);
    cudaFuncSetAttribute(wgemm<EPI_SPLIT>,   cudaFuncAttributeMaxDynamicSharedMemorySize, SMEM_BYTES);
    cudaFuncSetAttribute(wgemm<EPI_SPLIT_T>, cudaFuncAttributeMaxDynamicSharedMemorySize, SMEM_BYTES);

    // 1) split inputs into (hi, lo) bf16
    {
        const int n4x = MTOT * DIM / 4;
        split_kernel<<<n4x / 256, 256>>>(x, xhi, xlo, n4x);
        const int n4w = DIM * DIM / 4;
        split_kernel<<<n4w / 256, 256>>>(Wq, Wqhi, Wqlo, n4w);
        split_kernel<<<n4w / 256, 256>>>(Wk, Wkhi, Wklo, n4w);
        split_kernel<<<n4w / 256, 256>>>(Wv, Wvhi, Wvlo, n4w);
    }

    // 2) Q = x Wq^T, K = x Wk^T (split bf16); V = x Wv^T (transposed split)
    {
        dim3 g(DIM / 128, MTOT / 128, 1);
        wgemm<EPI_SPLIT><<<g, 256, SMEM_BYTES>>>(
            xhi, xlo, Wqhi, Wqlo, nullptr, Qhi, Qlo,
            DIM, DIM, DIM, DIM, 1.f, 0, 0, 0);
        wgemm<EPI_SPLIT><<<g, 256, SMEM_BYTES>>>(
            xhi, xlo, Wkhi, Wklo, nullptr, Khi, Klo,
            DIM, DIM, DIM, DIM, 1.f, 0, 0, 0);
        wgemm<EPI_SPLIT_T><<<g, 256, SMEM_BYTES>>>(
            xhi, xlo, Wvhi, Wvlo, nullptr, Vthi, Vtlo,
            DIM, DIM, DIM, MTOT, 1.f, 0, 0, 0);
    }

    // 3) S = (Q K^T) / 32, batched over 4
    {
        dim3 g(SEQ / 128, SEQ / 128, BATCH);
        wgemm<EPI_F32><<<g, 256, SMEM_BYTES>>>(
            Qhi, Qlo, Khi, Klo, S, nullptr, nullptr,
            DIM, DIM, DIM, SEQ, 0.03125f,
            (long long)SEQ * DIM, (long long)SEQ * DIM, (long long)SEQ * SEQ);
    }

    // 4) softmax -> split bf16 P
    softmax_split_kernel<<<BATCH * SEQ, 256>>>(S, Phi, Plo);

    // 5) out = P V  (B = Vt [DIM, MTOT], batch offset = b*SEQ columns)
    {
        dim3 g(DIM / 128, SEQ / 128, BATCH);
        wgemm<EPI_F32><<<g, 256, SMEM_BYTES>>>(
            Phi, Plo, Vthi, Vtlo, out, nullptr, nullptr,
            SEQ, SEQ, MTOT, DIM, 1.f,
            (long long)SEQ * SEQ, (long long)SEQ, (long long)SEQ * DIM);
    }
}

// round 7
// speedup vs baseline: 4.3512x; 1.4618x over previous
#include <cuda_runtime.h>
#include <cuda_fp16.h>
#include <cstdint>

#define BATCH 4
#define SEQ   2048
#define DIM   1024
#define MTOT  (BATCH * SEQ)

// ---------------------------------------------------------------------------
// Static device scratch (allocation-free per harness rules)
// Split (hi/lo) only for A-side operands: x, Q, P. Single fp16 for B-side:
// W_q/W_k/W_v, K, Vt.
// ---------------------------------------------------------------------------
__device__ __half g_xhi[(size_t)MTOT * DIM], g_xlo[(size_t)MTOT * DIM];
__device__ __half g_Wq[DIM * DIM], g_Wk[DIM * DIM], g_Wv[DIM * DIM];
__device__ __half g_Qhi[(size_t)MTOT * DIM], g_Qlo[(size_t)MTOT * DIM];
__device__ __half g_K[(size_t)MTOT * DIM];
__device__ __half g_Vt[(size_t)DIM * MTOT];          // [DIM, MTOT]
__device__ float  g_S[(size_t)BATCH * SEQ * SEQ];
__device__ __half g_Phi[(size_t)BATCH * SEQ * SEQ], g_Plo[(size_t)BATCH * SEQ * SEQ];

// ---------------------------------------------------------------------------
// PTX helpers (portable sm_80+ subset; tcgen05 is rejected on compute_103)
// ---------------------------------------------------------------------------
__device__ __forceinline__ uint32_t smem_u32(const void* p) {
    uint32_t a;
    asm("{ .reg .u64 t; cvta.to.shared.u64 t, %1; cvt.u32.u64 %0, t; }" : "=r"(a) : "l"(p));
    return a;
}

#define CP16(dst, src) \
    asm volatile("cp.async.cg.shared.global [%0], [%1], 16;" :: "r"(dst), "l"(src))
#define CP_COMMIT()  asm volatile("cp.async.commit_group;" ::: "memory")
#define CP_WAIT(n)   asm volatile("cp.async.wait_group %0;" :: "n"(n) : "memory")

#define LDSM_X4(r0, r1, r2, r3, addr)                                            \
    asm volatile("ldmatrix.sync.aligned.m8n8.x4.shared.b16 {%0,%1,%2,%3}, [%4];" \
                 : "=r"(r0), "=r"(r1), "=r"(r2), "=r"(r3) : "r"(addr))

#define MMA16816(d, a, b)                                                    \
    asm volatile("mma.sync.aligned.m16n8k16.row.col.f32.f16.f16.f32 "         \
                 "{%0,%1,%2,%3}, {%4,%5,%6,%7}, {%8,%9}, {%0,%1,%2,%3};"      \
                 : "+f"((d)[0]), "+f"((d)[1]), "+f"((d)[2]), "+f"((d)[3])     \
                 : "r"((a)[0]), "r"((a)[1]), "r"((a)[2]), "r"((a)[3]),        \
                   "r"((b)[0]), "r"((b)[1]))

// ---------------------------------------------------------------------------
// Split-A fp16 HMMA GEMM: C = scale * (A * B^T), A [M,K] as (hi, lo) fp16,
// B [N,K] single fp16 (K-major). D = Ahi*B + Alo*B, fp32 accumulate.
// Block tile 128x128, K-tile 64, 8 warps (warp tile 64x32), 3-stage cp.async,
// SW128-swizzled smem, ldmatrix fragment loads.
// ---------------------------------------------------------------------------
enum { EPI_F32 = 0, EPI_SPLIT = 1, EPI_F16 = 2, EPI_F16T = 3 };

constexpr int TILE_B  = 16384;            // one 128x64 fp16 tile (128B rows)
constexpr int STAGE_B = 3 * TILE_B;       // Ahi, Alo, B
constexpr int NSTAGE  = 3;
constexpr int SMEM_BYTES = NSTAGE * STAGE_B;  // 147456

template <int EPI>
__global__ __launch_bounds__(256, 1) void wgemm(
    const __half* __restrict__ Ahi, const __half* __restrict__ Alo,
    const __half* __restrict__ Bs,
    float* __restrict__ outF, __half* __restrict__ outHi, __half* __restrict__ outLo,
    int K, int ldA, int ldB, int ldC, float scale,
    long long sA, long long sB, long long sC)
{
    extern __shared__ __align__(1024) char smem[];
    const uint32_t sb = smem_u32(smem);

    const int tid = threadIdx.x, wid = tid >> 5, lane = tid & 31;
    const int bz = blockIdx.z;
    Ahi += (long long)bz * sA;  Alo += (long long)bz * sA;
    Bs  += (long long)bz * sB;
    if (EPI == EPI_F32) outF += (long long)bz * sC;
    else { outHi += (long long)bz * sC; if (EPI == EPI_SPLIT) outLo += (long long)bz * sC; }

    const int rowBase = blockIdx.y * 128;
    const int colBase = blockIdx.x * 128;
    const int warp_m = (wid >> 2) * 64;   // 2 warp-rows
    const int warp_n = (wid & 3) * 32;    // 4 warp-cols

    float acc[4][4][4];
#pragma unroll
    for (int mi = 0; mi < 4; mi++)
#pragma unroll
        for (int ni = 0; ni < 4; ni++)
#pragma unroll
            for (int q = 0; q < 4; q++) acc[mi][ni][q] = 0.f;

    const int nK = K >> 6;

    auto load_stage = [&](int i) {
        const uint32_t toff = sb + (i % NSTAGE) * STAGE_B;
        const int k0 = i << 6;
#pragma unroll
        for (int l = 0; l < 4; l++) {
            const int idx = tid + l * 256;
            const int r = idx >> 3, sg = idx & 7;
            const uint32_t d = toff + r * 128 + ((sg ^ (r & 7)) << 4);
            const size_t ka = (size_t)(rowBase + r) * ldA + k0 + sg * 8;
            const size_t kb = (size_t)(colBase + r) * ldB + k0 + sg * 8;
            CP16(d,              Ahi + ka);
            CP16(d + TILE_B,     Alo + ka);
            CP16(d + 2 * TILE_B, Bs  + kb);
        }
        CP_COMMIT();
    };

    load_stage(0);
    load_stage(1);

    for (int i = 0; i < nK; i++) {
        if (i + 1 < nK) CP_WAIT(1);
        else            CP_WAIT(0);
        __syncthreads();

        const uint32_t so = sb + (i % NSTAGE) * STAGE_B;

#pragma unroll
        for (int s = 0; s < 4; s++) {          // four k16 steps within k64
            uint32_t ah[4][4], al[4][4];
#pragma unroll
            for (int mi = 0; mi < 4; mi++) {
                const int r = warp_m + mi * 16 + (lane & 15);
                const int c = s * 2 + (lane >> 4);
                const uint32_t a = so + r * 128 + ((c ^ (r & 7)) << 4);
                LDSM_X4(ah[mi][0], ah[mi][1], ah[mi][2], ah[mi][3], a);
                LDSM_X4(al[mi][0], al[mi][1], al[mi][2], al[mi][3], a + TILE_B);
            }
            uint32_t bh[4][2];
#pragma unroll
            for (int nj = 0; nj < 2; nj++) {
                const int r = warp_n + nj * 16 + (lane & 7) + ((lane >> 4) << 3);
                const int c = s * 2 + ((lane >> 3) & 1);
                const uint32_t a = so + 2 * TILE_B + r * 128 + ((c ^ (r & 7)) << 4);
                uint32_t t0, t1, t2, t3;
                LDSM_X4(t0, t1, t2, t3, a);
                bh[nj * 2][0] = t0;     bh[nj * 2][1] = t1;
                bh[nj * 2 + 1][0] = t2; bh[nj * 2 + 1][1] = t3;
            }
#pragma unroll
            for (int mi = 0; mi < 4; mi++)
#pragma unroll
                for (int ni = 0; ni < 4; ni++) {
                    MMA16816(acc[mi][ni], ah[mi], bh[ni]);
                    MMA16816(acc[mi][ni], al[mi], bh[ni]);
                }
        }

        if (i + 2 < nK) load_stage(i + 2);   // writes stage (i-1)%3: safe, all
                                             // warps passed this iter's sync
    }

    // ---------------- epilogue ----------------
#pragma unroll
    for (int mi = 0; mi < 4; mi++) {
#pragma unroll
        for (int ni = 0; ni < 4; ni++) {
            const float* a = acc[mi][ni];
            const int row = rowBase + warp_m + mi * 16 + (lane >> 2);
            const int col = colBase + warp_n + ni * 8 + (lane & 3) * 2;
            if (EPI == EPI_F32) {
                float2 v0 = make_float2(a[0] * scale, a[1] * scale);
                float2 v1 = make_float2(a[2] * scale, a[3] * scale);
                *(float2*)&outF[(size_t)row * ldC + col] = v0;
                *(float2*)&outF[(size_t)(row + 8) * ldC + col] = v1;
            } else if (EPI == EPI_SPLIT) {
#pragma unroll
                for (int h = 0; h < 2; h++) {
                    const float d0 = a[h * 2 + 0], d1 = a[h * 2 + 1];
                    const __half h0 = __float2half(d0);
                    const __half h1 = __float2half(d1);
                    const __half l0 = __float2half(d0 - __half2float(h0));
                    const __half l1 = __float2half(d1 - __half2float(h1));
                    const size_t o = (size_t)(row + h * 8) * ldC + col;
                    *(__half2*)&outHi[o] = __halves2half2(h0, h1);
                    *(__half2*)&outLo[o] = __halves2half2(l0, l1);
                }
            } else if (EPI == EPI_F16) {
#pragma unroll
                for (int h = 0; h < 2; h++) {
                    const size_t o = (size_t)(row + h * 8) * ldC + col;
                    *(__half2*)&outHi[o] =
                        __halves2half2(__float2half(a[h * 2]), __float2half(a[h * 2 + 1]));
                }
            } else {  // EPI_F16T: out[col][row]
#pragma unroll
                for (int q = 0; q < 4; q++) {
                    const int r2 = row + ((q >> 1) << 3);
                    const int c2 = col + (q & 1);
                    outHi[(size_t)c2 * ldC + r2] = __float2half(a[q]);
                }
            }
        }
    }
}

// ---------------------------------------------------------------------------
// fp32 -> (hi, lo) fp16 split, vectorized
// ---------------------------------------------------------------------------
__global__ __launch_bounds__(256) void split_kernel(
    const float* __restrict__ in, __half* __restrict__ hi,
    __half* __restrict__ lo, int n4)
{
    const int i4 = blockIdx.x * 256 + threadIdx.x;
    if (i4 >= n4) return;
    const int i = i4 * 4;
    const float4 v = *(const float4*)&in[i];
    __align__(8) __half h[4];
    __align__(8) __half l[4];
    const float f[4] = {v.x, v.y, v.z, v.w};
#pragma unroll
    for (int q = 0; q < 4; q++) {
        h[q] = __float2half(f[q]);
        l[q] = __float2half(f[q] - __half2float(h[q]));
    }
    *(uint2*)&hi[i] = *(uint2*)h;
    *(uint2*)&lo[i] = *(uint2*)l;
}

// fp32 -> fp16 convert (weights), vectorized
__global__ __launch_bounds__(256) void convert_kernel(
    const float* __restrict__ in, __half* __restrict__ out, int n4)
{
    const int i4 = blockIdx.x * 256 + threadIdx.x;
    if (i4 >= n4) return;
    const int i = i4 * 4;
    const float4 v = *(const float4*)&in[i];
    __align__(8) __half h[4];
    h[0] = __float2half(v.x); h[1] = __float2half(v.y);
    h[2] = __float2half(v.z); h[3] = __float2half(v.w);
    *(uint2*)&out[i] = *(uint2*)h;
}

// ---------------------------------------------------------------------------
// Row softmax over SEQ=2048, emits split fp16 P
// ---------------------------------------------------------------------------
__global__ __launch_bounds__(256) void softmax_split_kernel(
    const float* __restrict__ S, __half* __restrict__ Phi, __half* __restrict__ Plo)
{
    const size_t off = (size_t)blockIdx.x * SEQ;
    const float* p = S + off;
    const int tid = threadIdx.x;

    float v[8];
    float lmax = -__FLT_MAX__;
#pragma unroll
    for (int l = 0; l < 8; l++) { v[l] = p[tid + l * 256]; lmax = fmaxf(lmax, v[l]); }

    __shared__ float red[8];
#pragma unroll
    for (int o = 16; o; o >>= 1) lmax = fmaxf(lmax, __shfl_xor_sync(~0u, lmax, o));
    if ((tid & 31) == 0) red[tid >> 5] = lmax;
    __syncthreads();
    if (tid == 0) {
        float m = red[0];
#pragma unroll
        for (int i = 1; i < 8; i++) m = fmaxf(m, red[i]);
        red[0] = m;
    }
    __syncthreads();
    const float m = red[0];
    __syncthreads();

    float lsum = 0.f;
#pragma unroll
    for (int l = 0; l < 8; l++) { v[l] = __expf(v[l] - m); lsum += v[l]; }
#pragma unroll
    for (int o = 16; o; o >>= 1) lsum += __shfl_xor_sync(~0u, lsum, o);
    if ((tid & 31) == 0) red[tid >> 5] = lsum;
    __syncthreads();
    if (tid == 0) {
        float s = red[0];
#pragma unroll
        for (int i = 1; i < 8; i++) s += red[i];
        red[0] = s;
    }
    __syncthreads();
    const float inv = 1.f / red[0];

#pragma unroll
    for (int l = 0; l < 8; l++) {
        const float w = v[l] * inv;
        const __half h = __float2half(w);
        Phi[off + tid + l * 256] = h;
        Plo[off + tid + l * 256] = __float2half(w - __half2float(h));
    }
}

// ---------------------------------------------------------------------------
extern "C" void kernel_launch(void* const* d_in, const int* in_sizes, int n_in,
                              void* d_out, int out_size)
{
    const float* x  = (const float*)d_in[0];
    const float* Wq = (const float*)d_in[1];
    const float* Wk = (const float*)d_in[2];
    const float* Wv = (const float*)d_in[3];
    float* out = (float*)d_out;

    __half *xhi, *xlo, *wq, *wk, *wv, *Qhi, *Qlo, *Kh, *Vt, *Phi, *Plo;
    float* S;
    cudaGetSymbolAddress((void**)&xhi, g_xhi); cudaGetSymbolAddress((void**)&xlo, g_xlo);
    cudaGetSymbolAddress((void**)&wq, g_Wq);   cudaGetSymbolAddress((void**)&wk, g_Wk);
    cudaGetSymbolAddress((void**)&wv, g_Wv);
    cudaGetSymbolAddress((void**)&Qhi, g_Qhi); cudaGetSymbolAddress((void**)&Qlo, g_Qlo);
    cudaGetSymbolAddress((void**)&Kh, g_K);    cudaGetSymbolAddress((void**)&Vt, g_Vt);
    cudaGetSymbolAddress((void**)&Phi, g_Phi); cudaGetSymbolAddress((void**)&Plo, g_Plo);
    cudaGetSymbolAddress((void**)&S, g_S);

    cudaFuncSetAttribute(wgemm<EPI_F32>,   cudaFuncAttributeMaxDynamicSharedMemorySize, SMEM_BYTES);
    cudaFuncSetAttribute(wgemm<EPI_SPLIT>, cudaFuncAttributeMaxDynamicSharedMemorySize, SMEM_BYTES);
    cudaFuncSetAttribute(wgemm<EPI_F16>,   cudaFuncAttributeMaxDynamicSharedMemorySize, SMEM_BYTES);
    cudaFuncSetAttribute(wgemm<EPI_F16T>,  cudaFuncAttributeMaxDynamicSharedMemorySize, SMEM_BYTES);

    // 1) x -> (hi, lo) fp16; W -> fp16
    {
        const int n4x = MTOT * DIM / 4;
        split_kernel<<<n4x / 256, 256>>>(x, xhi, xlo, n4x);
        const int n4w = DIM * DIM / 4;
        convert_kernel<<<n4w / 256, 256>>>(Wq, wq, n4w);
        convert_kernel<<<n4w / 256, 256>>>(Wk, wk, n4w);
        convert_kernel<<<n4w / 256, 256>>>(Wv, wv, n4w);
    }

    // 2) Q = x Wq^T (split out); K = x Wk^T (fp16); V = x Wv^T (fp16, transposed)
    {
        dim3 g(DIM / 128, MTOT / 128, 1);
        wgemm<EPI_SPLIT><<<g, 256, SMEM_BYTES>>>(
            xhi, xlo, wq, nullptr, Qhi, Qlo, DIM, DIM, DIM, DIM, 1.f, 0, 0, 0);
        wgemm<EPI_F16><<<g, 256, SMEM_BYTES>>>(
            xhi, xlo, wk, nullptr, Kh, nullptr, DIM, DIM, DIM, DIM, 1.f, 0, 0, 0);
        wgemm<EPI_F16T><<<g, 256, SMEM_BYTES>>>(
            xhi, xlo, wv, nullptr, Vt, nullptr, DIM, DIM, DIM, MTOT, 1.f, 0, 0, 0);
    }

    // 3) S = (Q K^T) / 32, batched over 4
    {
        dim3 g(SEQ / 128, SEQ / 128, BATCH);
        wgemm<EPI_F32><<<g, 256, SMEM_BYTES>>>(
            Qhi, Qlo, Kh, S, nullptr, nullptr,
            DIM, DIM, DIM, SEQ, 0.03125f,
            (long long)SEQ * DIM, (long long)SEQ * DIM, (long long)SEQ * SEQ);
    }

    // 4) softmax -> split fp16 P
    softmax_split_kernel<<<BATCH * SEQ, 256>>>(S, Phi, Plo);

    // 5) out = P V  (B = Vt [DIM, MTOT], batch column offset b*SEQ)
    {
        dim3 g(DIM / 128, SEQ / 128, BATCH);
        wgemm<EPI_F32><<<g, 256, SMEM_BYTES>>>(
            Phi, Plo, Vt, out, nullptr, nullptr,
            SEQ, SEQ, MTOT, DIM, 1.f,
            (long long)SEQ * SEQ, (long long)SEQ, (long long)SEQ * DIM);
    }
}

// round 8
// speedup vs baseline: 6.9349x; 1.5938x over previous
#include <cuda_runtime.h>
#include <cuda_fp16.h>
#include <cstdint>

#define BATCH 4
#define SEQ   2048
#define DIM   1024
#define MTOT  (BATCH * SEQ)

// ---------------------------------------------------------------------------
// Static device scratch (allocation-free per harness rules). Pure fp16 path.
// ---------------------------------------------------------------------------
__device__ __half g_x[(size_t)MTOT * DIM];
__device__ __half g_Wq[DIM * DIM], g_Wk[DIM * DIM], g_Wv[DIM * DIM];
__device__ __half g_Q[(size_t)MTOT * DIM];
__device__ __half g_K[(size_t)MTOT * DIM];
__device__ __half g_Vt[(size_t)DIM * MTOT];          // [DIM, MTOT]
__device__ float  g_S[(size_t)BATCH * SEQ * SEQ];
__device__ __half g_P[(size_t)BATCH * SEQ * SEQ];

// ---------------------------------------------------------------------------
// PTX helpers (portable sm_80+ subset; tcgen05 is rejected on compute_103)
// ---------------------------------------------------------------------------
__device__ __forceinline__ uint32_t smem_u32(const void* p) {
    uint32_t a;
    asm("{ .reg .u64 t; cvta.to.shared.u64 t, %1; cvt.u32.u64 %0, t; }" : "=r"(a) : "l"(p));
    return a;
}

#define CP16(dst, src) \
    asm volatile("cp.async.cg.shared.global [%0], [%1], 16;" :: "r"(dst), "l"(src))
#define CP_COMMIT()  asm volatile("cp.async.commit_group;" ::: "memory")
#define CP_WAIT(n)   asm volatile("cp.async.wait_group %0;" :: "n"(n) : "memory")

#define LDSM_X4(r0, r1, r2, r3, addr)                                            \
    asm volatile("ldmatrix.sync.aligned.m8n8.x4.shared.b16 {%0,%1,%2,%3}, [%4];" \
                 : "=r"(r0), "=r"(r1), "=r"(r2), "=r"(r3) : "r"(addr))

#define MMA16816(d, a, b)                                                    \
    asm volatile("mma.sync.aligned.m16n8k16.row.col.f32.f16.f16.f32 "         \
                 "{%0,%1,%2,%3}, {%4,%5,%6,%7}, {%8,%9}, {%0,%1,%2,%3};"      \
                 : "+f"((d)[0]), "+f"((d)[1]), "+f"((d)[2]), "+f"((d)[3])     \
                 : "r"((a)[0]), "r"((a)[1]), "r"((a)[2]), "r"((a)[3]),        \
                   "r"((b)[0]), "r"((b)[1]))

// ---------------------------------------------------------------------------
// fp16 HMMA GEMM: C = scale * (A * B^T), A [M,K], B [N,K], both fp16 K-major.
// Block tile 128x128, K-tile 64, 8 warps (warp tile 64x32), 4-stage cp.async,
// SW128-swizzled smem, ldmatrix fragment loads, fp32 accumulate.
// ---------------------------------------------------------------------------
enum { EPI_F32 = 0, EPI_F16 = 1, EPI_F16T = 2 };

constexpr int TILE_B  = 16384;            // one 128x64 fp16 tile (128B rows)
constexpr int STAGE_B = 2 * TILE_B;       // A, B
constexpr int NSTAGE  = 4;
constexpr int SMEM_BYTES = NSTAGE * STAGE_B;  // 131072

template <int EPI>
__global__ __launch_bounds__(256, 1) void wgemm(
    const __half* __restrict__ Ap, const __half* __restrict__ Bp,
    float* __restrict__ outF, __half* __restrict__ outH,
    int K, int ldA, int ldB, int ldC, float scale,
    long long sA, long long sB, long long sC)
{
    extern __shared__ __align__(1024) char smem[];
    const uint32_t sb = smem_u32(smem);

    const int tid = threadIdx.x, wid = tid >> 5, lane = tid & 31;
    const int bz = blockIdx.z;
    Ap += (long long)bz * sA;
    Bp += (long long)bz * sB;
    if (EPI == EPI_F32) outF += (long long)bz * sC;
    else                outH += (long long)bz * sC;

    const int rowBase = blockIdx.y * 128;
    const int colBase = blockIdx.x * 128;
    const int warp_m = (wid >> 2) * 64;   // 2 warp-rows
    const int warp_n = (wid & 3) * 32;    // 4 warp-cols

    float acc[4][4][4];
#pragma unroll
    for (int mi = 0; mi < 4; mi++)
#pragma unroll
        for (int ni = 0; ni < 4; ni++)
#pragma unroll
            for (int q = 0; q < 4; q++) acc[mi][ni][q] = 0.f;

    const int nK = K >> 6;

    auto load_stage = [&](int i) {
        const uint32_t toff = sb + (i % NSTAGE) * STAGE_B;
        const int k0 = i << 6;
#pragma unroll
        for (int l = 0; l < 4; l++) {
            const int idx = tid + l * 256;
            const int r = idx >> 3, sg = idx & 7;
            const uint32_t d = toff + r * 128 + ((sg ^ (r & 7)) << 4);
            CP16(d,          Ap + (size_t)(rowBase + r) * ldA + k0 + sg * 8);
            CP16(d + TILE_B, Bp + (size_t)(colBase + r) * ldB + k0 + sg * 8);
        }
        CP_COMMIT();
    };

    load_stage(0);
    load_stage(1);
    load_stage(2);

    for (int i = 0; i < nK; i++) {
        if (i + 2 < nK) CP_WAIT(2);
        else            CP_WAIT(0);
        __syncthreads();

        const uint32_t so = sb + (i % NSTAGE) * STAGE_B;

#pragma unroll
        for (int s = 0; s < 4; s++) {          // four k16 steps within k64
            uint32_t ah[4][4];
#pragma unroll
            for (int mi = 0; mi < 4; mi++) {
                const int r = warp_m + mi * 16 + (lane & 15);
                const int c = s * 2 + (lane >> 4);
                const uint32_t a = so + r * 128 + ((c ^ (r & 7)) << 4);
                LDSM_X4(ah[mi][0], ah[mi][1], ah[mi][2], ah[mi][3], a);
            }
            uint32_t bh[4][2];
#pragma unroll
            for (int nj = 0; nj < 2; nj++) {
                const int r = warp_n + nj * 16 + (lane & 7) + ((lane >> 4) << 3);
                const int c = s * 2 + ((lane >> 3) & 1);
                const uint32_t a = so + TILE_B + r * 128 + ((c ^ (r & 7)) << 4);
                uint32_t t0, t1, t2, t3;
                LDSM_X4(t0, t1, t2, t3, a);
                bh[nj * 2][0] = t0;     bh[nj * 2][1] = t1;
                bh[nj * 2 + 1][0] = t2; bh[nj * 2 + 1][1] = t3;
            }
#pragma unroll
            for (int mi = 0; mi < 4; mi++)
#pragma unroll
                for (int ni = 0; ni < 4; ni++)
                    MMA16816(acc[mi][ni], ah[mi], bh[ni]);
        }

        if (i + 3 < nK) load_stage(i + 3);   // overwrites stage (i-1)%4: safe,
                                             // all warps passed this iter's sync
    }

    // ---------------- epilogue ----------------
#pragma unroll
    for (int mi = 0; mi < 4; mi++) {
#pragma unroll
        for (int ni = 0; ni < 4; ni++) {
            const float* a = acc[mi][ni];
            const int row = rowBase + warp_m + mi * 16 + (lane >> 2);
            const int col = colBase + warp_n + ni * 8 + (lane & 3) * 2;
            if (EPI == EPI_F32) {
                float2 v0 = make_float2(a[0] * scale, a[1] * scale);
                float2 v1 = make_float2(a[2] * scale, a[3] * scale);
                *(float2*)&outF[(size_t)row * ldC + col] = v0;
                *(float2*)&outF[(size_t)(row + 8) * ldC + col] = v1;
            } else if (EPI == EPI_F16) {
#pragma unroll
                for (int h = 0; h < 2; h++) {
                    const size_t o = (size_t)(row + h * 8) * ldC + col;
                    *(__half2*)&outH[o] =
                        __halves2half2(__float2half(a[h * 2]), __float2half(a[h * 2 + 1]));
                }
            } else {  // EPI_F16T: out[col][row]
#pragma unroll
                for (int q = 0; q < 4; q++) {
                    const int r2 = row + ((q >> 1) << 3);
                    const int c2 = col + (q & 1);
                    outH[(size_t)c2 * ldC + r2] = __float2half(a[q]);
                }
            }
        }
    }
}

// ---------------------------------------------------------------------------
// fp32 -> fp16 convert, vectorized
// ---------------------------------------------------------------------------
__global__ __launch_bounds__(256) void convert_kernel(
    const float* __restrict__ in, __half* __restrict__ out, int n4)
{
    const int i4 = blockIdx.x * 256 + threadIdx.x;
    if (i4 >= n4) return;
    const int i = i4 * 4;
    const float4 v = *(const float4*)&in[i];
    __align__(8) __half h[4];
    h[0] = __float2half(v.x); h[1] = __float2half(v.y);
    h[2] = __float2half(v.z); h[3] = __float2half(v.w);
    *(uint2*)&out[i] = *(uint2*)h;
}

// ---------------------------------------------------------------------------
// Row softmax over SEQ=2048, emits fp16 P
// ---------------------------------------------------------------------------
__global__ __launch_bounds__(256) void softmax_kernel(
    const float* __restrict__ S, __half* __restrict__ P)
{
    const size_t off = (size_t)blockIdx.x * SEQ;
    const float* p = S + off;
    const int tid = threadIdx.x;

    float v[8];
    float lmax = -__FLT_MAX__;
#pragma unroll
    for (int l = 0; l < 8; l++) { v[l] = p[tid + l * 256]; lmax = fmaxf(lmax, v[l]); }

    __shared__ float red[8];
#pragma unroll
    for (int o = 16; o; o >>= 1) lmax = fmaxf(lmax, __shfl_xor_sync(~0u, lmax, o));
    if ((tid & 31) == 0) red[tid >> 5] = lmax;
    __syncthreads();
    if (tid == 0) {
        float m = red[0];
#pragma unroll
        for (int i = 1; i < 8; i++) m = fmaxf(m, red[i]);
        red[0] = m;
    }
    __syncthreads();
    const float m = red[0];
    __syncthreads();

    float lsum = 0.f;
#pragma unroll
    for (int l = 0; l < 8; l++) { v[l] = __expf(v[l] - m); lsum += v[l]; }
#pragma unroll
    for (int o = 16; o; o >>= 1) lsum += __shfl_xor_sync(~0u, lsum, o);
    if ((tid & 31) == 0) red[tid >> 5] = lsum;
    __syncthreads();
    if (tid == 0) {
        float s = red[0];
#pragma unroll
        for (int i = 1; i < 8; i++) s += red[i];
        red[0] = s;
    }
    __syncthreads();
    const float inv = 1.f / red[0];

#pragma unroll
    for (int l = 0; l < 8; l++)
        P[off + tid + l * 256] = __float2half(v[l] * inv);
}

// ---------------------------------------------------------------------------
extern "C" void kernel_launch(void* const* d_in, const int* in_sizes, int n_in,
                              void* d_out, int out_size)
{
    const float* x  = (const float*)d_in[0];
    const float* Wq = (const float*)d_in[1];
    const float* Wk = (const float*)d_in[2];
    const float* Wv = (const float*)d_in[3];
    float* out = (float*)d_out;

    __half *xh, *wq, *wk, *wv, *Qh, *Kh, *Vt, *Ph;
    float* S;
    cudaGetSymbolAddress((void**)&xh, g_x);
    cudaGetSymbolAddress((void**)&wq, g_Wq);   cudaGetSymbolAddress((void**)&wk, g_Wk);
    cudaGetSymbolAddress((void**)&wv, g_Wv);
    cudaGetSymbolAddress((void**)&Qh, g_Q);    cudaGetSymbolAddress((void**)&Kh, g_K);
    cudaGetSymbolAddress((void**)&Vt, g_Vt);   cudaGetSymbolAddress((void**)&Ph, g_P);
    cudaGetSymbolAddress((void**)&S, g_S);

    cudaFuncSetAttribute(wgemm<EPI_F32>,  cudaFuncAttributeMaxDynamicSharedMemorySize, SMEM_BYTES);
    cudaFuncSetAttribute(wgemm<EPI_F16>,  cudaFuncAttributeMaxDynamicSharedMemorySize, SMEM_BYTES);
    cudaFuncSetAttribute(wgemm<EPI_F16T>, cudaFuncAttributeMaxDynamicSharedMemorySize, SMEM_BYTES);

    // 1) x, W -> fp16
    {
        const int n4x = MTOT * DIM / 4;
        convert_kernel<<<n4x / 256, 256>>>(x, xh, n4x);
        const int n4w = DIM * DIM / 4;
        convert_kernel<<<n4w / 256, 256>>>(Wq, wq, n4w);
        convert_kernel<<<n4w / 256, 256>>>(Wk, wk, n4w);
        convert_kernel<<<n4w / 256, 256>>>(Wv, wv, n4w);
    }

    // 2) Q = x Wq^T; K = x Wk^T; V = x Wv^T (transposed store)
    {
        dim3 g(DIM / 128, MTOT / 128, 1);
        wgemm<EPI_F16><<<g, 256, SMEM_BYTES>>>(
            xh, wq, nullptr, Qh, DIM, DIM, DIM, DIM, 1.f, 0, 0, 0);
        wgemm<EPI_F16><<<g, 256, SMEM_BYTES>>>(
            xh, wk, nullptr, Kh, DIM, DIM, DIM, DIM, 1.f, 0, 0, 0);
        wgemm<EPI_F16T><<<g, 256, SMEM_BYTES>>>(
            xh, wv, nullptr, Vt, DIM, DIM, DIM, MTOT, 1.f, 0, 0, 0);
    }

    // 3) S = (Q K^T) / 32, batched over 4
    {
        dim3 g(SEQ / 128, SEQ / 128, BATCH);
        wgemm<EPI_F32><<<g, 256, SMEM_BYTES>>>(
            Qh, Kh, S, nullptr,
            DIM, DIM, DIM, SEQ, 0.03125f,
            (long long)SEQ * DIM, (long long)SEQ * DIM, (long long)SEQ * SEQ);
    }

    // 4) softmax -> fp16 P
    softmax_kernel<<<BATCH * SEQ, 256>>>(S, Ph);

    // 5) out = P V  (B = Vt [DIM, MTOT], batch column offset b*SEQ)
    {
        dim3 g(DIM / 128, SEQ / 128, BATCH);
        wgemm<EPI_F32><<<g, 256, SMEM_BYTES>>>(
            Ph, Vt, out, nullptr,
            SEQ, SEQ, MTOT, DIM, 1.f,
            (long long)SEQ * SEQ, (long long)SEQ, (long long)SEQ * DIM);
    }
}

// round 9
// speedup vs baseline: 8.4133x; 1.2132x over previous
#include <cuda_runtime.h>
#include <cuda_fp16.h>
#include <cstdint>

#define BATCH 4
#define SEQ   2048
#define DIM   1024
#define MTOT  (BATCH * SEQ)

// ---------------------------------------------------------------------------
// Static device scratch (allocation-free per harness rules). Pure fp16 path.
// ---------------------------------------------------------------------------
__device__ __half g_x[(size_t)MTOT * DIM];
__device__ __half g_W3[3 * DIM * DIM];               // [Wq; Wk; Wv] stacked
__device__ __half g_Q[(size_t)MTOT * DIM];
__device__ __half g_K[(size_t)MTOT * DIM];
__device__ __half g_Vt[(size_t)DIM * MTOT];          // [DIM, MTOT]
__device__ float  g_S[(size_t)BATCH * SEQ * SEQ];
__device__ __half g_P[(size_t)BATCH * SEQ * SEQ];

// ---------------------------------------------------------------------------
// PTX helpers (portable sm_80+ subset; tcgen05 is rejected on compute_103)
// ---------------------------------------------------------------------------
__device__ __forceinline__ uint32_t smem_u32(const void* p) {
    uint32_t a;
    asm("{ .reg .u64 t; cvta.to.shared.u64 t, %1; cvt.u32.u64 %0, t; }" : "=r"(a) : "l"(p));
    return a;
}

#define CP16(dst, src) \
    asm volatile("cp.async.cg.shared.global [%0], [%1], 16;" :: "r"(dst), "l"(src))
#define CP_COMMIT()  asm volatile("cp.async.commit_group;" ::: "memory")
#define CP_WAIT(n)   asm volatile("cp.async.wait_group %0;" :: "n"(n) : "memory")

#define LDSM_X4(r0, r1, r2, r3, addr)                                            \
    asm volatile("ldmatrix.sync.aligned.m8n8.x4.shared.b16 {%0,%1,%2,%3}, [%4];" \
                 : "=r"(r0), "=r"(r1), "=r"(r2), "=r"(r3) : "r"(addr))

#define MMA16816(d, a, b)                                                    \
    asm volatile("mma.sync.aligned.m16n8k16.row.col.f32.f16.f16.f32 "         \
                 "{%0,%1,%2,%3}, {%4,%5,%6,%7}, {%8,%9}, {%0,%1,%2,%3};"      \
                 : "+f"((d)[0]), "+f"((d)[1]), "+f"((d)[2]), "+f"((d)[3])     \
                 : "r"((a)[0]), "r"((a)[1]), "r"((a)[2]), "r"((a)[3]),        \
                   "r"((b)[0]), "r"((b)[1]))

// ---------------------------------------------------------------------------
// fp16 HMMA GEMM: C = scale * (A * B^T), A [M,K], B [N,K], both fp16 K-major.
// Block tile 128x128, 4 warps (warp tile 64x64), K-tile 64, 3-stage cp.async,
// SW128-swizzled smem, 2 CTAs/SM, fp32 accumulate.
// EPI_QKV routes output by column range: [0,1024)->Q, [1024,2048)->K,
// [2048,3072)->Vt (transposed store).
// ---------------------------------------------------------------------------
enum { EPI_F32 = 0, EPI_QKV = 1 };

constexpr int TILE_B  = 16384;            // one 128x64 fp16 tile (128B rows)
constexpr int STAGE_B = 2 * TILE_B;       // A, B
constexpr int NSTAGE  = 3;
constexpr int SMEM_BYTES = NSTAGE * STAGE_B;  // 98304

template <int EPI>
__global__ __launch_bounds__(128, 2) void wgemm(
    const __half* __restrict__ Ap, const __half* __restrict__ Bp,
    float* __restrict__ outF, __half* __restrict__ oQ,
    __half* __restrict__ oK, __half* __restrict__ oVt,
    int K, int ldA, int ldB, int ldC, float scale,
    long long sA, long long sB, long long sC)
{
    extern __shared__ __align__(1024) char smem[];
    const uint32_t sb = smem_u32(smem);

    const int tid = threadIdx.x, wid = tid >> 5, lane = tid & 31;
    const int bz = blockIdx.z;
    Ap += (long long)bz * sA;
    Bp += (long long)bz * sB;
    if (EPI == EPI_F32) outF += (long long)bz * sC;

    const int rowBase = blockIdx.y * 128;
    const int colBase = blockIdx.x * 128;
    const int warp_m = (wid >> 1) * 64;   // 2 warp-rows
    const int warp_n = (wid & 1) * 64;    // 2 warp-cols

    float acc[4][8][4];
#pragma unroll
    for (int mi = 0; mi < 4; mi++)
#pragma unroll
        for (int ni = 0; ni < 8; ni++)
#pragma unroll
            for (int q = 0; q < 4; q++) acc[mi][ni][q] = 0.f;

    const int nK = K >> 6;

    auto load_stage = [&](int i) {
        const uint32_t toff = sb + (i % NSTAGE) * STAGE_B;
        const int k0 = i << 6;
#pragma unroll
        for (int l = 0; l < 8; l++) {
            const int idx = tid + l * 128;
            const int r = idx >> 3, sg = idx & 7;
            const uint32_t d = toff + r * 128 + ((sg ^ (r & 7)) << 4);
            CP16(d,          Ap + (size_t)(rowBase + r) * ldA + k0 + sg * 8);
            CP16(d + TILE_B, Bp + (size_t)(colBase + r) * ldB + k0 + sg * 8);
        }
        CP_COMMIT();
    };

    load_stage(0);
    load_stage(1);

    for (int i = 0; i < nK; i++) {
        if (i + 1 < nK) CP_WAIT(1);
        else            CP_WAIT(0);
        __syncthreads();

        const uint32_t so = sb + (i % NSTAGE) * STAGE_B;

#pragma unroll
        for (int s = 0; s < 4; s++) {          // four k16 steps within k64
            uint32_t ah[4][4];
#pragma unroll
            for (int mi = 0; mi < 4; mi++) {
                const int r = warp_m + mi * 16 + (lane & 15);
                const int c = s * 2 + (lane >> 4);
                const uint32_t a = so + r * 128 + ((c ^ (r & 7)) << 4);
                LDSM_X4(ah[mi][0], ah[mi][1], ah[mi][2], ah[mi][3], a);
            }
            uint32_t bh[8][2];
#pragma unroll
            for (int nj = 0; nj < 4; nj++) {
                const int r = warp_n + nj * 16 + (lane & 7) + ((lane >> 4) << 3);
                const int c = s * 2 + ((lane >> 3) & 1);
                const uint32_t a = so + TILE_B + r * 128 + ((c ^ (r & 7)) << 4);
                uint32_t t0, t1, t2, t3;
                LDSM_X4(t0, t1, t2, t3, a);
                bh[nj * 2][0] = t0;     bh[nj * 2][1] = t1;
                bh[nj * 2 + 1][0] = t2; bh[nj * 2 + 1][1] = t3;
            }
#pragma unroll
            for (int mi = 0; mi < 4; mi++)
#pragma unroll
                for (int ni = 0; ni < 8; ni++)
                    MMA16816(acc[mi][ni], ah[mi], bh[ni]);
        }

        if (i + 2 < nK) load_stage(i + 2);   // overwrites stage (i-1)%3: safe,
                                             // all warps passed this iter's sync
    }

    // ---------------- epilogue ----------------
#pragma unroll
    for (int mi = 0; mi < 4; mi++) {
#pragma unroll
        for (int ni = 0; ni < 8; ni++) {
            const float* a = acc[mi][ni];
            const int row = rowBase + warp_m + mi * 16 + (lane >> 2);
            const int col = colBase + warp_n + ni * 8 + (lane & 3) * 2;
            if (EPI == EPI_F32) {
                float2 v0 = make_float2(a[0] * scale, a[1] * scale);
                float2 v1 = make_float2(a[2] * scale, a[3] * scale);
                *(float2*)&outF[(size_t)row * ldC + col] = v0;
                *(float2*)&outF[(size_t)(row + 8) * ldC + col] = v1;
            } else {  // EPI_QKV: route by column region (uniform per block)
                if (colBase < 1024) {
#pragma unroll
                    for (int h = 0; h < 2; h++)
                        *(__half2*)&oQ[(size_t)(row + h * 8) * DIM + col] =
                            __halves2half2(__float2half(a[h * 2]),
                                           __float2half(a[h * 2 + 1]));
                } else if (colBase < 2048) {
#pragma unroll
                    for (int h = 0; h < 2; h++)
                        *(__half2*)&oK[(size_t)(row + h * 8) * DIM + (col - 1024)] =
                            __halves2half2(__float2half(a[h * 2]),
                                           __float2half(a[h * 2 + 1]));
                } else {
#pragma unroll
                    for (int q = 0; q < 4; q++) {
                        const int r2 = row + ((q >> 1) << 3);
                        const int c2 = col + (q & 1) - 2048;
                        oVt[(size_t)c2 * MTOT + r2] = __float2half(a[q]);
                    }
                }
            }
        }
    }
}

// ---------------------------------------------------------------------------
// fp32 -> fp16 convert, vectorized
// ---------------------------------------------------------------------------
__global__ __launch_bounds__(256) void convert_kernel(
    const float* __restrict__ in, __half* __restrict__ out, int n4)
{
    const int i4 = blockIdx.x * 256 + threadIdx.x;
    if (i4 >= n4) return;
    const int i = i4 * 4;
    const float4 v = *(const float4*)&in[i];
    __align__(8) __half h[4];
    h[0] = __float2half(v.x); h[1] = __float2half(v.y);
    h[2] = __float2half(v.z); h[3] = __float2half(v.w);
    *(uint2*)&out[i] = *(uint2*)h;
}

// ---------------------------------------------------------------------------
// Row softmax over SEQ=2048, emits fp16 P
// ---------------------------------------------------------------------------
__global__ __launch_bounds__(256) void softmax_kernel(
    const float* __restrict__ S, __half* __restrict__ P)
{
    const size_t off = (size_t)blockIdx.x * SEQ;
    const float* p = S + off;
    const int tid = threadIdx.x;

    float v[8];
    float lmax = -__FLT_MAX__;
#pragma unroll
    for (int l = 0; l < 8; l++) { v[l] = p[tid + l * 256]; lmax = fmaxf(lmax, v[l]); }

    __shared__ float red[8];
#pragma unroll
    for (int o = 16; o; o >>= 1) lmax = fmaxf(lmax, __shfl_xor_sync(~0u, lmax, o));
    if ((tid & 31) == 0) red[tid >> 5] = lmax;
    __syncthreads();
    if (tid == 0) {
        float m = red[0];
#pragma unroll
        for (int i = 1; i < 8; i++) m = fmaxf(m, red[i]);
        red[0] = m;
    }
    __syncthreads();
    const float m = red[0];
    __syncthreads();

    float lsum = 0.f;
#pragma unroll
    for (int l = 0; l < 8; l++) { v[l] = __expf(v[l] - m); lsum += v[l]; }
#pragma unroll
    for (int o = 16; o; o >>= 1) lsum += __shfl_xor_sync(~0u, lsum, o);
    if ((tid & 31) == 0) red[tid >> 5] = lsum;
    __syncthreads();
    if (tid == 0) {
        float s = red[0];
#pragma unroll
        for (int i = 1; i < 8; i++) s += red[i];
        red[0] = s;
    }
    __syncthreads();
    const float inv = 1.f / red[0];

#pragma unroll
    for (int l = 0; l < 8; l++)
        P[off + tid + l * 256] = __float2half(v[l] * inv);
}

// ---------------------------------------------------------------------------
extern "C" void kernel_launch(void* const* d_in, const int* in_sizes, int n_in,
                              void* d_out, int out_size)
{
    const float* x  = (const float*)d_in[0];
    const float* Wq = (const float*)d_in[1];
    const float* Wk = (const float*)d_in[2];
    const float* Wv = (const float*)d_in[3];
    float* out = (float*)d_out;

    __half *xh, *w3, *Qh, *Kh, *Vt, *Ph;
    float* S;
    cudaGetSymbolAddress((void**)&xh, g_x);
    cudaGetSymbolAddress((void**)&w3, g_W3);
    cudaGetSymbolAddress((void**)&Qh, g_Q);   cudaGetSymbolAddress((void**)&Kh, g_K);
    cudaGetSymbolAddress((void**)&Vt, g_Vt);  cudaGetSymbolAddress((void**)&Ph, g_P);
    cudaGetSymbolAddress((void**)&S, g_S);

    cudaFuncSetAttribute(wgemm<EPI_F32>, cudaFuncAttributeMaxDynamicSharedMemorySize, SMEM_BYTES);
    cudaFuncSetAttribute(wgemm<EPI_QKV>, cudaFuncAttributeMaxDynamicSharedMemorySize, SMEM_BYTES);

    // 1) x -> fp16; W -> fp16 stacked [Wq; Wk; Wv]
    {
        const int n4x = MTOT * DIM / 4;
        convert_kernel<<<n4x / 256, 256>>>(x, xh, n4x);
        const int n4w = DIM * DIM / 4;
        convert_kernel<<<n4w / 256, 256>>>(Wq, w3,               n4w);
        convert_kernel<<<n4w / 256, 256>>>(Wk, w3 + DIM * DIM,   n4w);
        convert_kernel<<<n4w / 256, 256>>>(Wv, w3 + 2 * DIM * DIM, n4w);
    }

    // 2) fused QKV: [Q | K | V] = x @ W3^T, epilogue-routed (V transposed)
    {
        dim3 g(3 * DIM / 128, MTOT / 128, 1);
        wgemm<EPI_QKV><<<g, 128, SMEM_BYTES>>>(
            xh, w3, nullptr, Qh, Kh, Vt,
            DIM, DIM, DIM, 0, 1.f, 0, 0, 0);
    }

    // 3) S = (Q K^T) / 32, batched over 4
    {
        dim3 g(SEQ / 128, SEQ / 128, BATCH);
        wgemm<EPI_F32><<<g, 128, SMEM_BYTES>>>(
            Qh, Kh, S, nullptr, nullptr, nullptr,
            DIM, DIM, DIM, SEQ, 0.03125f,
            (long long)SEQ * DIM, (long long)SEQ * DIM, (long long)SEQ * SEQ);
    }

    // 4) softmax -> fp16 P
    softmax_kernel<<<BATCH * SEQ, 256>>>(S, Ph);

    // 5) out = P V  (B = Vt [DIM, MTOT], batch column offset b*SEQ)
    {
        dim3 g(DIM / 128, SEQ / 128, BATCH);
        wgemm<EPI_F32><<<g, 128, SMEM_BYTES>>>(
            Ph, Vt, out, nullptr, nullptr, nullptr,
            SEQ, SEQ, MTOT, DIM, 1.f,
            (long long)SEQ * SEQ, (long long)SEQ, (long long)SEQ * DIM);
    }
}

// round 11
// speedup vs baseline: 8.5558x; 1.0169x over previous
#include <cuda_runtime.h>
#include <cuda_fp16.h>
#include <cstdint>

#define BATCH 4
#define SEQ   2048
#define DIM   1024
#define MTOT  (BATCH * SEQ)

// ---------------------------------------------------------------------------
// Static device scratch (allocation-free per harness rules). Pure fp16 path.
// ---------------------------------------------------------------------------
__device__ __half g_x[(size_t)MTOT * DIM];
__device__ __half g_W3[3 * DIM * DIM];               // [Wq; Wk; Wv] stacked
__device__ __half g_Q[(size_t)MTOT * DIM];
__device__ __half g_K[(size_t)MTOT * DIM];
__device__ __half g_Vt[(size_t)DIM * MTOT];          // [DIM, MTOT]
__device__ __half g_S[(size_t)BATCH * SEQ * SEQ];    // fp16 scores
__device__ __half g_P[(size_t)BATCH * SEQ * SEQ];

// ---------------------------------------------------------------------------
// PTX helpers (portable sm_80+ subset; tcgen05 is rejected on compute_103)
// ---------------------------------------------------------------------------
__device__ __forceinline__ uint32_t smem_u32(const void* p) {
    uint32_t a;
    asm("{ .reg .u64 t; cvta.to.shared.u64 t, %1; cvt.u32.u64 %0, t; }" : "=r"(a) : "l"(p));
    return a;
}

#define CP16(dst, src) \
    asm volatile("cp.async.cg.shared.global [%0], [%1], 16;" :: "r"(dst), "l"(src))
#define CP_COMMIT()  asm volatile("cp.async.commit_group;" ::: "memory")
#define CP_WAIT(n)   asm volatile("cp.async.wait_group %0;" :: "n"(n) : "memory")

#define LDSM_X4(r0, r1, r2, r3, addr)                                            \
    asm volatile("ldmatrix.sync.aligned.m8n8.x4.shared.b16 {%0,%1,%2,%3}, [%4];" \
                 : "=r"(r0), "=r"(r1), "=r"(r2), "=r"(r3) : "r"(addr))

#define MMA16816(d, a, b)                                                    \
    asm volatile("mma.sync.aligned.m16n8k16.row.col.f32.f16.f16.f32 "         \
                 "{%0,%1,%2,%3}, {%4,%5,%6,%7}, {%8,%9}, {%0,%1,%2,%3};"      \
                 : "+f"((d)[0]), "+f"((d)[1]), "+f"((d)[2]), "+f"((d)[3])     \
                 : "r"((a)[0]), "r"((a)[1]), "r"((a)[2]), "r"((a)[3]),        \
                   "r"((b)[0]), "r"((b)[1]))

// ---------------------------------------------------------------------------
// fp16 HMMA GEMM: C = scale * (A * B^T), A [M,K], B [N,K], both fp16 K-major.
// Block tile 128x128, 4 warps (warp tile 64x64), K-tile 64, 3-stage cp.async
// issued at loop top (full-compute overlap), SW128-swizzled smem, 2 CTAs/SM.
// EPI_F32:  scaled fp32 out (PV)
// EPI_F16S: scaled fp16 out (S scores)
// EPI_QKV:  route by column range: [0,1024)->Q, [1024,2048)->K,
//           [2048,3072)->Vt (transposed store).
// ---------------------------------------------------------------------------
enum { EPI_F32 = 0, EPI_F16S = 1, EPI_QKV = 2 };

constexpr int TILE_B  = 16384;            // one 128x64 fp16 tile (128B rows)
constexpr int STAGE_B = 2 * TILE_B;       // A, B
constexpr int NSTAGE  = 3;
constexpr int SMEM_BYTES = NSTAGE * STAGE_B;  // 98304

template <int EPI>
__global__ __launch_bounds__(128, 2) void wgemm(
    const __half* __restrict__ Ap, const __half* __restrict__ Bp,
    float* __restrict__ outF, __half* __restrict__ oQ,
    __half* __restrict__ oK, __half* __restrict__ oVt,
    int K, int ldA, int ldB, int ldC, float scale,
    long long sA, long long sB, long long sC)
{
    extern __shared__ __align__(1024) char smem[];
    const uint32_t sb = smem_u32(smem);

    const int tid = threadIdx.x, wid = tid >> 5, lane = tid & 31;
    const int bz = blockIdx.z;
    Ap += (long long)bz * sA;
    Bp += (long long)bz * sB;
    if (EPI == EPI_F32) outF += (long long)bz * sC;
    else if (EPI == EPI_F16S) oQ += (long long)bz * sC;

    const int rowBase = blockIdx.y * 128;
    const int colBase = blockIdx.x * 128;
    const int warp_m = (wid >> 1) * 64;   // 2 warp-rows
    const int warp_n = (wid & 1) * 64;    // 2 warp-cols

    float acc[4][8][4];
#pragma unroll
    for (int mi = 0; mi < 4; mi++)
#pragma unroll
        for (int ni = 0; ni < 8; ni++)
#pragma unroll
            for (int q = 0; q < 4; q++) acc[mi][ni][q] = 0.f;

    const int nK = K >> 6;

    auto load_stage = [&](int i) {
        const uint32_t toff = sb + (i % NSTAGE) * STAGE_B;
        const int k0 = i << 6;
#pragma unroll
        for (int l = 0; l < 8; l++) {
            const int idx = tid + l * 128;
            const int r = idx >> 3, sg = idx & 7;
            const uint32_t d = toff + r * 128 + ((sg ^ (r & 7)) << 4);
            CP16(d,          Ap + (size_t)(rowBase + r) * ldA + k0 + sg * 8);
            CP16(d + TILE_B, Bp + (size_t)(colBase + r) * ldB + k0 + sg * 8);
        }
        CP_COMMIT();
    };

    load_stage(0);
    load_stage(1);

    for (int i = 0; i < nK; i++) {
        if (i + 1 < nK) CP_WAIT(1);
        else            CP_WAIT(0);
        __syncthreads();

        // Issue stage i+2 NOW: overwrites buffer of stage i-1, whose readers
        // all passed the barrier above. DMA overlaps the full MMA block below.
        if (i + 2 < nK) load_stage(i + 2);

        const uint32_t so = sb + (i % NSTAGE) * STAGE_B;

#pragma unroll
        for (int s = 0; s < 4; s++) {          // four k16 steps within k64
            uint32_t ah[4][4];
#pragma unroll
            for (int mi = 0; mi < 4; mi++) {
                const int r = warp_m + mi * 16 + (lane & 15);
                const int c = s * 2 + (lane >> 4);
                const uint32_t a = so + r * 128 + ((c ^ (r & 7)) << 4);
                LDSM_X4(ah[mi][0], ah[mi][1], ah[mi][2], ah[mi][3], a);
            }
            uint32_t bh[8][2];
#pragma unroll
            for (int nj = 0; nj < 4; nj++) {
                const int r = warp_n + nj * 16 + (lane & 7) + ((lane >> 4) << 3);
                const int c = s * 2 + ((lane >> 3) & 1);
                const uint32_t a = so + TILE_B + r * 128 + ((c ^ (r & 7)) << 4);
                uint32_t t0, t1, t2, t3;
                LDSM_X4(t0, t1, t2, t3, a);
                bh[nj * 2][0] = t0;     bh[nj * 2][1] = t1;
                bh[nj * 2 + 1][0] = t2; bh[nj * 2 + 1][1] = t3;
            }
#pragma unroll
            for (int mi = 0; mi < 4; mi++)
#pragma unroll
                for (int ni = 0; ni < 8; ni++)
                    MMA16816(acc[mi][ni], ah[mi], bh[ni]);
        }
    }

    // ---------------- epilogue ----------------
#pragma unroll
    for (int mi = 0; mi < 4; mi++) {
#pragma unroll
        for (int ni = 0; ni < 8; ni++) {
            const float* a = acc[mi][ni];
            const int row = rowBase + warp_m + mi * 16 + (lane >> 2);
            const int col = colBase + warp_n + ni * 8 + (lane & 3) * 2;
            if (EPI == EPI_F32) {
                float2 v0 = make_float2(a[0] * scale, a[1] * scale);
                float2 v1 = make_float2(a[2] * scale, a[3] * scale);
                *(float2*)&outF[(size_t)row * ldC + col] = v0;
                *(float2*)&outF[(size_t)(row + 8) * ldC + col] = v1;
            } else if (EPI == EPI_F16S) {
#pragma unroll
                for (int h = 0; h < 2; h++)
                    *(__half2*)&oQ[(size_t)(row + h * 8) * ldC + col] =
                        __halves2half2(__float2half(a[h * 2] * scale),
                                       __float2half(a[h * 2 + 1] * scale));
            } else {  // EPI_QKV: route by column region (uniform per block)
                if (colBase < 1024) {
#pragma unroll
                    for (int h = 0; h < 2; h++)
                        *(__half2*)&oQ[(size_t)(row + h * 8) * DIM + col] =
                            __halves2half2(__float2half(a[h * 2]),
                                           __float2half(a[h * 2 + 1]));
                } else if (colBase < 2048) {
#pragma unroll
                    for (int h = 0; h < 2; h++)
                        *(__half2*)&oK[(size_t)(row + h * 8) * DIM + (col - 1024)] =
                            __halves2half2(__float2half(a[h * 2]),
                                           __float2half(a[h * 2 + 1]));
                } else {
#pragma unroll
                    for (int q = 0; q < 4; q++) {
                        const int r2 = row + ((q >> 1) << 3);
                        const int c2 = col + (q & 1) - 2048;
                        oVt[(size_t)c2 * MTOT + r2] = __float2half(a[q]);
                    }
                }
            }
        }
    }
}

// ---------------------------------------------------------------------------
// fp32 -> fp16 convert, vectorized (x)
// ---------------------------------------------------------------------------
__global__ __launch_bounds__(256) void convert_kernel(
    const float* __restrict__ in, __half* __restrict__ out, int n4)
{
    const int i4 = blockIdx.x * 256 + threadIdx.x;
    if (i4 >= n4) return;
    const int i = i4 * 4;
    const float4 v = *(const float4*)&in[i];
    __align__(8) __half h[4];
    h[0] = __float2half(v.x); h[1] = __float2half(v.y);
    h[2] = __float2half(v.z); h[3] = __float2half(v.w);
    *(uint2*)&out[i] = *(uint2*)h;
}

// All three weights in one launch; routed by index range.
__global__ __launch_bounds__(256) void convertW_kernel(
    const float* __restrict__ wq, const float* __restrict__ wk,
    const float* __restrict__ wv, __half* __restrict__ out)
{
    constexpr int N4 = DIM * DIM / 4;  // per-weight float4 count
    const int g = blockIdx.x * 256 + threadIdx.x;   // 0 .. 3*N4-1
    const float* src = (g < N4) ? wq : (g < 2 * N4) ? wk : wv;
    const int local = (g < N4) ? g : (g < 2 * N4) ? g - N4 : g - 2 * N4;
    const float4 v = *(const float4*)&src[local * 4];
    __align__(8) __half h[4];
    h[0] = __float2half(v.x); h[1] = __float2half(v.y);
    h[2] = __float2half(v.z); h[3] = __float2half(v.w);
    *(uint2*)&out[g * 4] = *(uint2*)h;
}

// ---------------------------------------------------------------------------
// Row softmax over SEQ=2048 fp16 scores -> fp16 P, vectorized uint4 IO
// ---------------------------------------------------------------------------
__global__ __launch_bounds__(256) void softmax_kernel(
    const __half* __restrict__ S, __half* __restrict__ P)
{
    const size_t off = (size_t)blockIdx.x * SEQ;
    const int tid = threadIdx.x;

    uint4 raw = *(const uint4*)(S + off + tid * 8);
    __half hv[8];
    *(uint4*)hv = raw;

    float v[8];
    float lmax = -__FLT_MAX__;
#pragma unroll
    for (int l = 0; l < 8; l++) { v[l] = __half2float(hv[l]); lmax = fmaxf(lmax, v[l]); }

    __shared__ float red[8];
#pragma unroll
    for (int o = 16; o; o >>= 1) lmax = fmaxf(lmax, __shfl_xor_sync(~0u, lmax, o));
    if ((tid & 31) == 0) red[tid >> 5] = lmax;
    __syncthreads();
    if (tid == 0) {
        float m = red[0];
#pragma unroll
        for (int i = 1; i < 8; i++) m = fmaxf(m, red[i]);
        red[0] = m;
    }
    __syncthreads();
    const float m = red[0];
    __syncthreads();

    float lsum = 0.f;
#pragma unroll
    for (int l = 0; l < 8; l++) { v[l] = __expf(v[l] - m); lsum += v[l]; }
#pragma unroll
    for (int o = 16; o; o >>= 1) lsum += __shfl_xor_sync(~0u, lsum, o);
    if ((tid & 31) == 0) red[tid >> 5] = lsum;
    __syncthreads();
    if (tid == 0) {
        float s = red[0];
#pragma unroll
        for (int i = 1; i < 8; i++) s += red[i];
        red[0] = s;
    }
    __syncthreads();
    const float inv = 1.f / red[0];

#pragma unroll
    for (int l = 0; l < 8; l++) hv[l] = __float2half(v[l] * inv);
    *(uint4*)(P + off + tid * 8) = *(uint4*)hv;
}

// ---------------------------------------------------------------------------
extern "C" void kernel_launch(void* const* d_in, const int* in_sizes, int n_in,
                              void* d_out, int out_size)
{
    const float* x  = (const float*)d_in[0];
    const float* Wq = (const float*)d_in[1];
    const float* Wk = (const float*)d_in[2];
    const float* Wv = (const float*)d_in[3];
    float* out = (float*)d_out;

    __half *xh, *w3, *Qh, *Kh, *Vt, *Ph, *S;
    cudaGetSymbolAddress((void**)&xh, g_x);
    cudaGetSymbolAddress((void**)&w3, g_W3);
    cudaGetSymbolAddress((void**)&Qh, g_Q);   cudaGetSymbolAddress((void**)&Kh, g_K);
    cudaGetSymbolAddress((void**)&Vt, g_Vt);  cudaGetSymbolAddress((void**)&Ph, g_P);
    cudaGetSymbolAddress((void**)&S, g_S);

    cudaFuncSetAttribute(wgemm<EPI_F32>,  cudaFuncAttributeMaxDynamicSharedMemorySize, SMEM_BYTES);
    cudaFuncSetAttribute(wgemm<EPI_F16S>, cudaFuncAttributeMaxDynamicSharedMemorySize, SMEM_BYTES);
    cudaFuncSetAttribute(wgemm<EPI_QKV>,  cudaFuncAttributeMaxDynamicSharedMemorySize, SMEM_BYTES);

    // launch 0: x -> fp16
    {
        const int n4x = MTOT * DIM / 4;
        convert_kernel<<<n4x / 256, 256>>>(x, xh, n4x);
    }
    // launch 1: all weights -> fp16 stacked [Wq; Wk; Wv]
    {
        const int n4w3 = 3 * DIM * DIM / 4;
        convertW_kernel<<<n4w3 / 256, 256>>>(Wq, Wk, Wv, w3);
    }
    // launch 2: fused QKV: [Q | K | V] = x @ W3^T (V transposed store)
    {
        dim3 g(3 * DIM / 128, MTOT / 128, 1);
        wgemm<EPI_QKV><<<g, 128, SMEM_BYTES>>>(
            xh, w3, nullptr, Qh, Kh, Vt,
            DIM, DIM, DIM, 0, 1.f, 0, 0, 0);
    }
    // launch 3: S = (Q K^T) / 32, fp16 out, batched over 4
    {
        dim3 g(SEQ / 128, SEQ / 128, BATCH);
        wgemm<EPI_F16S><<<g, 128, SMEM_BYTES>>>(
            Qh, Kh, nullptr, S, nullptr, nullptr,
            DIM, DIM, DIM, SEQ, 0.03125f,
            (long long)SEQ * DIM, (long long)SEQ * DIM, (long long)SEQ * SEQ);
    }
    // launch 4: softmax -> fp16 P
    softmax_kernel<<<BATCH * SEQ, 256>>>(S, Ph);

    // launch 5: out = P V  (B = Vt [DIM, MTOT], batch column offset b*SEQ)
    {
        dim3 g(DIM / 128, SEQ / 128, BATCH);
        wgemm<EPI_F32><<<g, 128, SMEM_BYTES>>>(
            Ph, Vt, out, nullptr, nullptr, nullptr,
            SEQ, SEQ, MTOT, DIM, 1.f,
            (long long)SEQ * SEQ, (long long)SEQ, (long long)SEQ * DIM);
    }
}